// round 4
// baseline (speedup 1.0000x reference)
#include <cuda_runtime.h>
#include <math.h>

#define NN 50000
#define EE 800000
#define DH 128
#define DOUT 40

// ---------------- scratch (device globals; no allocation allowed) ----------------
__device__ float g_bufA[NN * DH];
__device__ float g_bufB[NN * DH];
__device__ float g_bufC[NN * DH];
__device__ float g_sum[DH];
__device__ float g_sqsum[DH];
__device__ float g_scale[DH];
__device__ float g_shift[DH];

// ---------------- scatter-add: one warp per edge, float4 vector reductions ----------------
__global__ void scatter_add_kernel(const float* __restrict__ X,
                                   const int* __restrict__ ei,
                                   float* __restrict__ agg, int nedges) {
    int gw = (blockIdx.x * blockDim.x + threadIdx.x) >> 5;
    int lane = threadIdx.x & 31;
    if (gw >= nedges) return;
    int src = __ldg(&ei[gw]);
    int dst = __ldg(&ei[nedges + gw]);
    src = min(max(src, 0), NN - 1);
    dst = min(max(dst, 0), NN - 1);
    float4 v = __ldg((const float4*)X + (size_t)src * 32 + lane);
    float* p = agg + (size_t)dst * DH + lane * 4;
    asm volatile("red.global.add.v4.f32 [%0], {%1, %2, %3, %4};"
                 :: "l"(p), "f"(v.x), "f"(v.y), "f"(v.z), "f"(v.w)
                 : "memory");
}

// ---------------- stats helpers ----------------
__global__ void zero_stats_kernel() {
    int c = threadIdx.x;
    if (c < DH) { g_sum[c] = 0.f; g_sqsum[c] = 0.f; }
}

__global__ void finalize_bn_kernel(const float* __restrict__ gamma,
                                   const float* __restrict__ beta, float invN) {
    int c = threadIdx.x;
    if (c < DH) {
        float mu  = g_sum[c] * invN;
        float var = g_sqsum[c] * invN - mu * mu;
        float rs  = rsqrtf(var + 1e-5f);
        float sc  = rs * __ldg(&gamma[c]);
        g_scale[c] = sc;
        g_shift[c] = __ldg(&beta[c]) - mu * sc;
    }
}

// apply BN (precomputed scale/shift) + ReLU in place, vectorized
__global__ void bn_relu_kernel(float4* __restrict__ T, int n4) {
    int i = blockIdx.x * blockDim.x + threadIdx.x;
    if (i >= n4) return;
    int c4 = i & 31;
    float4 v = T[i];
    float4 sc = ((const float4*)g_scale)[c4];
    float4 sh = ((const float4*)g_shift)[c4];
    v.x = fmaxf(v.x * sc.x + sh.x, 0.f);
    v.y = fmaxf(v.y * sc.y + sh.y, 0.f);
    v.z = fmaxf(v.z * sc.z + sh.z, 0.f);
    v.w = fmaxf(v.w * sc.w + sh.w, 0.f);
    T[i] = v;
}

// ---------------- packed-f32x2 GEMM: Y[N,128] = X[N,128] @ W[128,128] + b ----------
// 256 threads, 64 rows/block. Thread = 4 rows (rg = t>>4) x 8 cols (cg = t&15).
// W loaded as ulonglong2 -> each u64 is already a packed (c, c+1) f32x2 pair.
// X scalar replicated (x,x) once per row per k, reused across 4 col-pairs.
#define FMA2(acc, a, b) asm("fma.rn.f32x2 %0, %1, %2, %0;" : "+l"(acc) : "l"(a), "l"(b))
#define PACK2(d, s)     asm("mov.b64 %0, {%1, %1};" : "=l"(d) : "f"(s))
#define UNPACK2(lo, hi, s) asm("mov.b64 {%0, %1}, %2;" : "=f"(lo), "=f"(hi) : "l"(s))

template <bool RELU, bool STATS>
__global__ void __launch_bounds__(256) gemm128_kernel(
    const float* __restrict__ X, const float* __restrict__ W,
    const float* __restrict__ B, float* __restrict__ Y, int nrows)
{
    int t  = threadIdx.x;
    int cg = t & 15;        // cols [cg*8, cg*8+8)
    int rg = t >> 4;        // 16 row groups x 4 rows
    int row0 = blockIdx.x * 64 + rg * 4;

    const float4*     X4 = (const float4*)X;
    const ulonglong2* W2 = (const ulonglong2*)W;   // 32 ulonglong2 per W row

    int  rowc[4];
    bool val[4];
#pragma unroll
    for (int r = 0; r < 4; r++) {
        int rr = row0 + r;
        val[r]  = rr < nrows;
        rowc[r] = (val[r] ? rr : 0) * 32;
    }

    unsigned long long acc[4][4];   // [row][col-pair], each = f32x2
#pragma unroll
    for (int r = 0; r < 4; r++)
#pragma unroll
        for (int j = 0; j < 4; j++) acc[r][j] = 0ull;

    int wbase = cg * 2;

#pragma unroll 2
    for (int k4 = 0; k4 < 32; k4++) {
        float4 xq[4];
#pragma unroll
        for (int r = 0; r < 4; r++) xq[r] = X4[rowc[r] + k4];

#pragma unroll
        for (int kk = 0; kk < 4; kk++) {
            int k = k4 * 4 + kk;
            ulonglong2 wa = W2[k * 32 + wbase];      // pairs (c0,c1),(c2,c3)
            ulonglong2 wb = W2[k * 32 + wbase + 1];  // pairs (c4,c5),(c6,c7)
#pragma unroll
            for (int r = 0; r < 4; r++) {
                float xs = (kk == 0) ? xq[r].x : (kk == 1) ? xq[r].y
                         : (kk == 2) ? xq[r].z : xq[r].w;
                unsigned long long xr;
                PACK2(xr, xs);
                FMA2(acc[r][0], xr, wa.x);
                FMA2(acc[r][1], xr, wa.y);
                FMA2(acc[r][2], xr, wb.x);
                FMA2(acc[r][3], xr, wb.y);
            }
        }
    }

    // bias for 8 cols
    float4 b0 = ((const float4*)B)[cg * 2];
    float4 b1 = ((const float4*)B)[cg * 2 + 1];
    float bias[8] = {b0.x, b0.y, b0.z, b0.w, b1.x, b1.y, b1.z, b1.w};

    float colsum[8], colsq[8];
#pragma unroll
    for (int j = 0; j < 8; j++) { colsum[j] = 0.f; colsq[j] = 0.f; }

#pragma unroll
    for (int r = 0; r < 4; r++) {
        if (!val[r]) continue;
        float y[8];
#pragma unroll
        for (int j = 0; j < 4; j++) {
            UNPACK2(y[j * 2], y[j * 2 + 1], acc[r][j]);
        }
#pragma unroll
        for (int j = 0; j < 8; j++) {
            y[j] += bias[j];
            if (RELU) y[j] = fmaxf(y[j], 0.f);
            if (STATS) { colsum[j] += y[j]; colsq[j] += y[j] * y[j]; }
        }
        float4 o0; o0.x = y[0]; o0.y = y[1]; o0.z = y[2]; o0.w = y[3];
        float4 o1; o1.x = y[4]; o1.y = y[5]; o1.z = y[6]; o1.w = y[7];
        ((float4*)Y)[rowc[r] + cg * 2]     = o0;
        ((float4*)Y)[rowc[r] + cg * 2 + 1] = o1;
    }

    if (STATS) {
        __shared__ float ssum[16][128];
        __shared__ float ssq[16][128];
#pragma unroll
        for (int j = 0; j < 8; j++) {
            ssum[rg][cg * 8 + j] = colsum[j];
            ssq[rg][cg * 8 + j]  = colsq[j];
        }
        __syncthreads();
        if (t < 128) {
            float s = 0.f;
#pragma unroll
            for (int g = 0; g < 16; g++) s += ssum[g][t];
            atomicAdd(&g_sum[t], s);
        } else {
            int c = t - 128;
            float s = 0.f;
#pragma unroll
            for (int g = 0; g < 16; g++) s += ssq[g][c];
            atomicAdd(&g_sqsum[c], s);
        }
    }
}

// ---------------- head GEMM: logits[N,40] = X[N,128] @ W[128,40] + b ----------------
__global__ void __launch_bounds__(320) gemm40_kernel(
    const float* __restrict__ X, const float* __restrict__ W,
    const float* __restrict__ B, float* __restrict__ Y, int nrows)
{
    int t  = threadIdx.x;
    int rg = t / 10;
    int cg = t - rg * 10;
    int row0 = blockIdx.x * 128 + rg * 4;

    const float4* X4 = (const float4*)X;
    const float4* W4 = (const float4*)W;

    int  rowc[4];
    bool val[4];
#pragma unroll
    for (int r = 0; r < 4; r++) {
        int rr = row0 + r;
        val[r]  = rr < nrows;
        rowc[r] = val[r] ? rr : 0;
    }

    float acc[4][4];
#pragma unroll
    for (int r = 0; r < 4; r++)
#pragma unroll
        for (int j = 0; j < 4; j++) acc[r][j] = 0.f;

#pragma unroll 4
    for (int k = 0; k < 128; k += 4) {
        float4 w0 = W4[(k + 0) * 10 + cg];
        float4 w1 = W4[(k + 1) * 10 + cg];
        float4 w2 = W4[(k + 2) * 10 + cg];
        float4 w3 = W4[(k + 3) * 10 + cg];
#pragma unroll
        for (int r = 0; r < 4; r++) {
            float4 xv = X4[rowc[r] * 32 + (k >> 2)];
            acc[r][0] += xv.x * w0.x; acc[r][0] += xv.y * w1.x;
            acc[r][0] += xv.z * w2.x; acc[r][0] += xv.w * w3.x;
            acc[r][1] += xv.x * w0.y; acc[r][1] += xv.y * w1.y;
            acc[r][1] += xv.z * w2.y; acc[r][1] += xv.w * w3.y;
            acc[r][2] += xv.x * w0.z; acc[r][2] += xv.y * w1.z;
            acc[r][2] += xv.z * w2.z; acc[r][2] += xv.w * w3.z;
            acc[r][3] += xv.x * w0.w; acc[r][3] += xv.y * w1.w;
            acc[r][3] += xv.z * w2.w; acc[r][3] += xv.w * w3.w;
        }
    }

    float4 b4 = ((const float4*)B)[cg];
#pragma unroll
    for (int r = 0; r < 4; r++) {
        if (!val[r]) continue;
        float4 o;
        o.x = acc[r][0] + b4.x;
        o.y = acc[r][1] + b4.y;
        o.z = acc[r][2] + b4.z;
        o.w = acc[r][3] + b4.w;
        ((float4*)Y)[rowc[r] * 10 + cg] = o;
    }
}

// ---------------- log-softmax over 40 columns, one row per thread ----------------
__global__ void logsoftmax40_kernel(const float* __restrict__ L, float* __restrict__ out, int nrows) {
    int row = blockIdx.x * blockDim.x + threadIdx.x;
    if (row >= nrows) return;
    const float4* l4 = (const float4*)(L + (size_t)row * DOUT);
    float v[DOUT];
#pragma unroll
    for (int i = 0; i < 10; i++) {
        float4 a = __ldg(&l4[i]);
        v[i * 4 + 0] = a.x; v[i * 4 + 1] = a.y; v[i * 4 + 2] = a.z; v[i * 4 + 3] = a.w;
    }
    float m = v[0];
#pragma unroll
    for (int j = 1; j < DOUT; j++) m = fmaxf(m, v[j]);
    float s = 0.f;
#pragma unroll
    for (int j = 0; j < DOUT; j++) s += expf(v[j] - m);
    float lse = logf(s) + m;
    float4* o4 = (float4*)(out + (size_t)row * DOUT);
#pragma unroll
    for (int i = 0; i < 10; i++) {
        float4 o;
        o.x = v[i * 4 + 0] - lse; o.y = v[i * 4 + 1] - lse;
        o.z = v[i * 4 + 2] - lse; o.w = v[i * 4 + 3] - lse;
        o4[i] = o;
    }
}

// ---------------- host launch ----------------
extern "C" void kernel_launch(void* const* d_in, const int* in_sizes, int n_in,
                              void* d_out, int out_size) {
    const float* x   = (const float*)d_in[0];
    const int*   ei  = (const int*)d_in[1];   // int32
    const float* W1a = (const float*)d_in[2];
    const float* b1a = (const float*)d_in[3];
    const float* g1  = (const float*)d_in[4];
    const float* be1 = (const float*)d_in[5];
    const float* W2a = (const float*)d_in[6];
    const float* b2a = (const float*)d_in[7];
    const float* W1b = (const float*)d_in[8];
    const float* b1b = (const float*)d_in[9];
    const float* g2  = (const float*)d_in[10];
    const float* be2 = (const float*)d_in[11];
    const float* W2b = (const float*)d_in[12];
    const float* b2b = (const float*)d_in[13];
    const float* Wl1 = (const float*)d_in[14];
    const float* bl1 = (const float*)d_in[15];
    const float* Wl2 = (const float*)d_in[16];
    const float* bl2 = (const float*)d_in[17];
    float* out = (float*)d_out;

    float *pA, *pB, *pC;
    cudaGetSymbolAddress((void**)&pA, g_bufA);
    cudaGetSymbolAddress((void**)&pB, g_bufB);
    cudaGetSymbolAddress((void**)&pC, g_bufC);

    const size_t bufBytes = (size_t)NN * DH * sizeof(float);
    const int n4       = NN * 32;
    const int copyGrid = (n4 + 255) / 256;
    const int scatGrid = (EE + 7) / 8;
    const int gemmGrid = (NN + 63) / 64;
    const float invN = 1.0f / (float)NN;

    // ---- conv1 ----
    cudaMemcpyAsync(pA, x, bufBytes, cudaMemcpyDeviceToDevice);
    scatter_add_kernel<<<scatGrid, 256>>>(x, ei, pA, EE);
    zero_stats_kernel<<<1, 128>>>();
    gemm128_kernel<false, true><<<gemmGrid, 256>>>(pA, W1a, b1a, pB, NN);
    finalize_bn_kernel<<<1, 128>>>(g1, be1, invN);
    bn_relu_kernel<<<copyGrid, 256>>>((float4*)pB, n4);
    gemm128_kernel<true, false><<<gemmGrid, 256>>>(pB, W2a, b2a, pC, NN);

    // ---- conv2 ----
    cudaMemcpyAsync(pA, pC, bufBytes, cudaMemcpyDeviceToDevice);
    scatter_add_kernel<<<scatGrid, 256>>>(pC, ei, pA, EE);
    zero_stats_kernel<<<1, 128>>>();
    gemm128_kernel<false, true><<<gemmGrid, 256>>>(pA, W1b, b1b, pB, NN);
    finalize_bn_kernel<<<1, 128>>>(g2, be2, invN);
    bn_relu_kernel<<<copyGrid, 256>>>((float4*)pB, n4);
    gemm128_kernel<true, false><<<gemmGrid, 256>>>(pB, W2b, b2b, pC, NN);

    // ---- head ----
    gemm128_kernel<true, false><<<gemmGrid, 256>>>(pC, Wl1, bl1, pA, NN);
    gemm40_kernel<<<(NN + 127) / 128, 320>>>(pA, Wl2, bl2, pB, NN);
    logsoftmax40_kernel<<<(NN + 255) / 256, 256>>>(pB, out, NN);
}

// round 6
// speedup vs baseline: 1.4885x; 1.4885x over previous
#include <cuda_runtime.h>
#include <cuda_bf16.h>
#include <mma.h>
#include <math.h>
#include <stdint.h>

using namespace nvcuda;

#define NN 50000
#define EE 800000
#define DH 128
#define DOUT 40
#define WLD 136   // padded leading dim for bf16 tiles

// ---------------- scratch (device globals; no allocation allowed) ----------------
__device__ float g_bufA[NN * DH];
__device__ float g_bufB[NN * DH];
__device__ float g_bufC[NN * DH];
__device__ float g_sum[DH];
__device__ float g_sqsum[DH];
__device__ float g_scale[DH];
__device__ float g_shift[DH];
// 5 weight matrices (W1a, W2a, W1b, W2b, Wl1) as bf16 hi/lo, padded [128][136]
__device__ __nv_bfloat16 g_Wbf[5][2][128 * WLD];

// ---------------- W prep: float [K=128][N=128] -> bf16 hi/lo padded tiles ----------
__global__ void prep_w_kernel(const float* W0, const float* W1, const float* W2,
                              const float* W3, const float* W4) {
    const float* Ws[5] = {W0, W1, W2, W3, W4};
    const float* W = Ws[blockIdx.x];
    __nv_bfloat16* hi = g_Wbf[blockIdx.x][0];
    __nv_bfloat16* lo = g_Wbf[blockIdx.x][1];
    for (int idx = threadIdx.x; idx < 128 * 128; idx += blockDim.x) {
        int k = idx >> 7;
        int n = idx & 127;
        float w = __ldg(&W[idx]);
        __nv_bfloat16 h = __float2bfloat16(w);
        __nv_bfloat16 l = __float2bfloat16(w - __bfloat162float(h));
        hi[k * WLD + n] = h;
        lo[k * WLD + n] = l;
    }
}

// ---------------- tensor-core GEMM: Y[N,128] = X[N,128] @ W[128,128] + b ------------
// 256 threads (8 warps), 128 rows/CTA. bf16 hi/lo 3-term split, fp32 accum.
// smem: [0,512) bias | [512, 512+4*34816) Ahi/Alo/Bhi/Blo bf16 tiles (128 x 136)
//       output stage reuses [512, ...) as float tile (128 x 132).
static const int GSM_TOTAL = 512 + 4 * 128 * WLD * 2;   // 139776

template <bool RELU>
__global__ void __launch_bounds__(256) gemm_wmma_kernel(
    const float* __restrict__ X,
    const __nv_bfloat16* __restrict__ Whi,
    const __nv_bfloat16* __restrict__ Wlo,
    const float* __restrict__ Bias,
    float* __restrict__ Y, int nrows)
{
    extern __shared__ char smem[];
    float* sbias = (float*)smem;
    __nv_bfloat16* Ahi = (__nv_bfloat16*)(smem + 512);
    __nv_bfloat16* Alo = Ahi + 128 * WLD;
    __nv_bfloat16* Bhi = Alo + 128 * WLD;
    __nv_bfloat16* Blo = Bhi + 128 * WLD;
    float* sout = (float*)(smem + 512);   // reused after MMA

    int tid  = threadIdx.x;
    int row0 = blockIdx.x * 128;

    if (tid < 128) sbias[tid] = __ldg(&Bias[tid]);

    // copy W hi/lo tiles: 128*136 bf16 = 34816 B = 2176 uint4 each
    {
        const uint4* sh = (const uint4*)Whi;
        const uint4* sl = (const uint4*)Wlo;
        uint4* dh = (uint4*)Bhi;
        uint4* dl = (uint4*)Blo;
#pragma unroll
        for (int i = 0; i < 9; i++) {
            int j = tid + i * 256;
            if (j < 2176) { dh[j] = __ldg(&sh[j]); dl[j] = __ldg(&sl[j]); }
        }
    }

    // convert X tile -> bf16 hi/lo (zero-fill beyond nrows)
    {
        const float4* X4 = (const float4*)X;
#pragma unroll
        for (int i = 0; i < 16; i++) {
            int idx = tid + i * 256;          // 4096 float4 = 128x128 tile
            int r  = idx >> 5;
            int c4 = idx & 31;
            int grow = row0 + r;
            float4 v = make_float4(0.f, 0.f, 0.f, 0.f);
            if (grow < nrows) v = __ldg(&X4[(size_t)grow * 32 + c4]);
            __nv_bfloat16 h0 = __float2bfloat16(v.x), h1 = __float2bfloat16(v.y),
                          h2 = __float2bfloat16(v.z), h3 = __float2bfloat16(v.w);
            __nv_bfloat16 l0 = __float2bfloat16(v.x - __bfloat162float(h0));
            __nv_bfloat16 l1 = __float2bfloat16(v.y - __bfloat162float(h1));
            __nv_bfloat16 l2 = __float2bfloat16(v.z - __bfloat162float(h2));
            __nv_bfloat16 l3 = __float2bfloat16(v.w - __bfloat162float(h3));
            __nv_bfloat16* ph = Ahi + r * WLD + c4 * 4;
            __nv_bfloat16* pl = Alo + r * WLD + c4 * 4;
            ph[0] = h0; ph[1] = h1; ph[2] = h2; ph[3] = h3;
            pl[0] = l0; pl[1] = l1; pl[2] = l2; pl[3] = l3;
        }
    }
    __syncthreads();

    // MMA: warp w -> rows (w&3)*32..+32, cols (w>>2)*64..+64
    int w  = tid >> 5;
    int wr = (w & 3) * 32;
    int wc = (w >> 2) * 64;

    wmma::fragment<wmma::accumulator, 16, 16, 16, float> acc[2][4];
#pragma unroll
    for (int i = 0; i < 2; i++)
#pragma unroll
        for (int j = 0; j < 4; j++) wmma::fill_fragment(acc[i][j], 0.f);

#pragma unroll
    for (int k = 0; k < 8; k++) {
        wmma::fragment<wmma::matrix_a, 16, 16, 16, __nv_bfloat16, wmma::row_major> ah[2], al[2];
        wmma::fragment<wmma::matrix_b, 16, 16, 16, __nv_bfloat16, wmma::row_major> bh[4], bl[4];
#pragma unroll
        for (int i = 0; i < 2; i++) {
            wmma::load_matrix_sync(ah[i], Ahi + (wr + 16 * i) * WLD + k * 16, WLD);
            wmma::load_matrix_sync(al[i], Alo + (wr + 16 * i) * WLD + k * 16, WLD);
        }
#pragma unroll
        for (int j = 0; j < 4; j++) {
            wmma::load_matrix_sync(bh[j], Bhi + (k * 16) * WLD + wc + 16 * j, WLD);
            wmma::load_matrix_sync(bl[j], Blo + (k * 16) * WLD + wc + 16 * j, WLD);
        }
#pragma unroll
        for (int i = 0; i < 2; i++)
#pragma unroll
            for (int j = 0; j < 4; j++) {
                wmma::mma_sync(acc[i][j], ah[i], bh[j], acc[i][j]);
                wmma::mma_sync(acc[i][j], ah[i], bl[j], acc[i][j]);
                wmma::mma_sync(acc[i][j], al[i], bh[j], acc[i][j]);
            }
    }
    __syncthreads();   // all warps done reading bf16 tiles before reuse as float

    // stage accumulators to smem float tile (ld 132)
#pragma unroll
    for (int i = 0; i < 2; i++)
#pragma unroll
        for (int j = 0; j < 4; j++)
            wmma::store_matrix_sync(sout + (wr + 16 * i) * 132 + wc + 16 * j,
                                    acc[i][j], 132, wmma::mem_row_major);
    __syncthreads();

    // bias + relu + global write
    {
        float4* Y4 = (float4*)Y;
#pragma unroll
        for (int i = 0; i < 16; i++) {
            int idx = tid + i * 256;
            int r  = idx >> 5;
            int c4 = idx & 31;
            int grow = row0 + r;
            if (grow >= nrows) continue;
            float4 b = ((const float4*)sbias)[c4];
            float4 v = ((const float4*)(sout + r * 132))[c4];
            v.x += b.x; v.y += b.y; v.z += b.z; v.w += b.w;
            if (RELU) {
                v.x = fmaxf(v.x, 0.f); v.y = fmaxf(v.y, 0.f);
                v.z = fmaxf(v.z, 0.f); v.w = fmaxf(v.w, 0.f);
            }
            Y4[(size_t)grow * 32 + c4] = v;
        }
    }
}

// ---------------- column stats over Y [NN,128] ----------------
__global__ void __launch_bounds__(256) stats_kernel(const float* __restrict__ Y) {
    int t = threadIdx.x;
    int c4 = t & 31;
    int rg = t >> 5;
    const float4* Y4 = (const float4*)Y;
    float4 s = make_float4(0.f, 0.f, 0.f, 0.f);
    float4 q = make_float4(0.f, 0.f, 0.f, 0.f);
    for (int row = blockIdx.x * 8 + rg; row < NN; row += gridDim.x * 8) {
        float4 v = __ldg(&Y4[(size_t)row * 32 + c4]);
        s.x += v.x; s.y += v.y; s.z += v.z; s.w += v.w;
        q.x += v.x * v.x; q.y += v.y * v.y; q.z += v.z * v.z; q.w += v.w * v.w;
    }
    __shared__ float ssum[8][128];
    __shared__ float ssq[8][128];
    ssum[rg][c4*4+0] = s.x; ssum[rg][c4*4+1] = s.y; ssum[rg][c4*4+2] = s.z; ssum[rg][c4*4+3] = s.w;
    ssq[rg][c4*4+0]  = q.x; ssq[rg][c4*4+1]  = q.y; ssq[rg][c4*4+2]  = q.z; ssq[rg][c4*4+3]  = q.w;
    __syncthreads();
    if (t < 128) {
        float a = 0.f;
#pragma unroll
        for (int g = 0; g < 8; g++) a += ssum[g][t];
        atomicAdd(&g_sum[t], a);
    } else {
        int c = t - 128;
        float a = 0.f;
#pragma unroll
        for (int g = 0; g < 8; g++) a += ssq[g][c];
        atomicAdd(&g_sqsum[c], a);
    }
}

// ---------------- copy / scatter / BN helpers (known-good from R3) ----------------
__global__ void copy4_kernel(float4* __restrict__ dst, const float4* __restrict__ src, int n4) {
    int i = blockIdx.x * blockDim.x + threadIdx.x;
    if (i < n4) dst[i] = src[i];
}

__global__ void scatter_add_kernel(const float* __restrict__ X,
                                   const int* __restrict__ ei,
                                   float* __restrict__ agg, int nedges) {
    int gw = (blockIdx.x * blockDim.x + threadIdx.x) >> 5;
    int lane = threadIdx.x & 31;
    if (gw >= nedges) return;
    int src = __ldg(&ei[gw]);
    int dst = __ldg(&ei[nedges + gw]);
    src = min(max(src, 0), NN - 1);
    dst = min(max(dst, 0), NN - 1);
    float4 v = __ldg((const float4*)X + (size_t)src * 32 + lane);
    float* p = agg + (size_t)dst * DH + lane * 4;
    asm volatile("red.global.add.v4.f32 [%0], {%1, %2, %3, %4};"
                 :: "l"(p), "f"(v.x), "f"(v.y), "f"(v.z), "f"(v.w)
                 : "memory");
}

__global__ void zero_stats_kernel() {
    int c = threadIdx.x;
    if (c < DH) { g_sum[c] = 0.f; g_sqsum[c] = 0.f; }
}

__global__ void finalize_bn_kernel(const float* __restrict__ gamma,
                                   const float* __restrict__ beta, float invN) {
    int c = threadIdx.x;
    if (c < DH) {
        float mu  = g_sum[c] * invN;
        float var = g_sqsum[c] * invN - mu * mu;
        float rs  = rsqrtf(var + 1e-5f);
        float sc  = rs * __ldg(&gamma[c]);
        g_scale[c] = sc;
        g_shift[c] = __ldg(&beta[c]) - mu * sc;
    }
}

__global__ void bn_relu_kernel(float4* __restrict__ T, int n4) {
    int i = blockIdx.x * blockDim.x + threadIdx.x;
    if (i >= n4) return;
    int c4 = i & 31;
    float4 v = T[i];
    float4 sc = ((const float4*)g_scale)[c4];
    float4 sh = ((const float4*)g_shift)[c4];
    v.x = fmaxf(v.x * sc.x + sh.x, 0.f);
    v.y = fmaxf(v.y * sc.y + sh.y, 0.f);
    v.z = fmaxf(v.z * sc.z + sh.z, 0.f);
    v.w = fmaxf(v.w * sc.w + sh.w, 0.f);
    T[i] = v;
}

// ---------------- head GEMM: logits[N,40] = X[N,128] @ W[128,40] + b ----------------
__global__ void __launch_bounds__(320) gemm40_kernel(
    const float* __restrict__ X, const float* __restrict__ W,
    const float* __restrict__ B, float* __restrict__ Y, int nrows)
{
    int t  = threadIdx.x;
    int rg = t / 10;
    int cg = t - rg * 10;
    int row0 = blockIdx.x * 128 + rg * 4;

    const float4* X4 = (const float4*)X;
    const float4* W4 = (const float4*)W;

    int  rowc[4];
    bool val[4];
#pragma unroll
    for (int r = 0; r < 4; r++) {
        int rr = row0 + r;
        val[r]  = rr < nrows;
        rowc[r] = val[r] ? rr : 0;
    }

    float acc[4][4];
#pragma unroll
    for (int r = 0; r < 4; r++)
#pragma unroll
        for (int j = 0; j < 4; j++) acc[r][j] = 0.f;

#pragma unroll 4
    for (int k = 0; k < 128; k += 4) {
        float4 w0 = W4[(k + 0) * 10 + cg];
        float4 w1 = W4[(k + 1) * 10 + cg];
        float4 w2 = W4[(k + 2) * 10 + cg];
        float4 w3 = W4[(k + 3) * 10 + cg];
#pragma unroll
        for (int r = 0; r < 4; r++) {
            float4 xv = X4[rowc[r] * 32 + (k >> 2)];
            acc[r][0] += xv.x * w0.x; acc[r][0] += xv.y * w1.x;
            acc[r][0] += xv.z * w2.x; acc[r][0] += xv.w * w3.x;
            acc[r][1] += xv.x * w0.y; acc[r][1] += xv.y * w1.y;
            acc[r][1] += xv.z * w2.y; acc[r][1] += xv.w * w3.y;
            acc[r][2] += xv.x * w0.z; acc[r][2] += xv.y * w1.z;
            acc[r][2] += xv.z * w2.z; acc[r][2] += xv.w * w3.z;
            acc[r][3] += xv.x * w0.w; acc[r][3] += xv.y * w1.w;
            acc[r][3] += xv.z * w2.w; acc[r][3] += xv.w * w3.w;
        }
    }

    float4 b4 = ((const float4*)B)[cg];
#pragma unroll
    for (int r = 0; r < 4; r++) {
        if (!val[r]) continue;
        float4 o;
        o.x = acc[r][0] + b4.x;
        o.y = acc[r][1] + b4.y;
        o.z = acc[r][2] + b4.z;
        o.w = acc[r][3] + b4.w;
        ((float4*)Y)[rowc[r] * 10 + cg] = o;
    }
}

// ---------------- log-softmax over 40 columns, one row per thread ----------------
__global__ void logsoftmax40_kernel(const float* __restrict__ L, float* __restrict__ out, int nrows) {
    int row = blockIdx.x * blockDim.x + threadIdx.x;
    if (row >= nrows) return;
    const float4* l4 = (const float4*)(L + (size_t)row * DOUT);
    float v[DOUT];
#pragma unroll
    for (int i = 0; i < 10; i++) {
        float4 a = __ldg(&l4[i]);
        v[i * 4 + 0] = a.x; v[i * 4 + 1] = a.y; v[i * 4 + 2] = a.z; v[i * 4 + 3] = a.w;
    }
    float m = v[0];
#pragma unroll
    for (int j = 1; j < DOUT; j++) m = fmaxf(m, v[j]);
    float s = 0.f;
#pragma unroll
    for (int j = 0; j < DOUT; j++) s += expf(v[j] - m);
    float lse = logf(s) + m;
    float4* o4 = (float4*)(out + (size_t)row * DOUT);
#pragma unroll
    for (int i = 0; i < 10; i++) {
        float4 o;
        o.x = v[i * 4 + 0] - lse; o.y = v[i * 4 + 1] - lse;
        o.z = v[i * 4 + 2] - lse; o.w = v[i * 4 + 3] - lse;
        o4[i] = o;
    }
}

// ---------------- host launch ----------------
extern "C" void kernel_launch(void* const* d_in, const int* in_sizes, int n_in,
                              void* d_out, int out_size) {
    const float* x   = (const float*)d_in[0];
    const int*   ei  = (const int*)d_in[1];   // int32
    const float* W1a = (const float*)d_in[2];
    const float* b1a = (const float*)d_in[3];
    const float* g1  = (const float*)d_in[4];
    const float* be1 = (const float*)d_in[5];
    const float* W2a = (const float*)d_in[6];
    const float* b2a = (const float*)d_in[7];
    const float* W1b = (const float*)d_in[8];
    const float* b1b = (const float*)d_in[9];
    const float* g2  = (const float*)d_in[10];
    const float* be2 = (const float*)d_in[11];
    const float* W2b = (const float*)d_in[12];
    const float* b2b = (const float*)d_in[13];
    const float* Wl1 = (const float*)d_in[14];
    const float* bl1 = (const float*)d_in[15];
    const float* Wl2 = (const float*)d_in[16];
    const float* bl2 = (const float*)d_in[17];
    float* out = (float*)d_out;

    float *pA, *pB, *pC;
    cudaGetSymbolAddress((void**)&pA, g_bufA);
    cudaGetSymbolAddress((void**)&pB, g_bufB);
    cudaGetSymbolAddress((void**)&pC, g_bufC);
    __nv_bfloat16* wt;
    cudaGetSymbolAddress((void**)&wt, g_Wbf);

    cudaFuncSetAttribute(gemm_wmma_kernel<false>, cudaFuncAttributeMaxDynamicSharedMemorySize, GSM_TOTAL);
    cudaFuncSetAttribute(gemm_wmma_kernel<true>,  cudaFuncAttributeMaxDynamicSharedMemorySize, GSM_TOTAL);

    const int n4       = NN * 32;
    const int copyGrid = (n4 + 255) / 256;
    const int scatGrid = (EE + 7) / 8;
    const int tcGrid   = (NN + 127) / 128;     // 391
    const float invN = 1.0f / (float)NN;
    const size_t wpage = (size_t)128 * WLD;    // elements per hi/lo tile

    // weight pages: 0=W1a 1=W2a 2=W1b 3=W2b 4=Wl1
    prep_w_kernel<<<5, 256>>>(W1a, W2a, W1b, W2b, Wl1);
#define WHI(p) (wt + (size_t)(p) * 2 * wpage)
#define WLO(p) (wt + (size_t)(p) * 2 * wpage + wpage)

    // ---- conv1 ----
    copy4_kernel<<<copyGrid, 256>>>((float4*)pA, (const float4*)x, n4);
    scatter_add_kernel<<<scatGrid, 256>>>(x, ei, pA, EE);
    zero_stats_kernel<<<1, 128>>>();
    gemm_wmma_kernel<false><<<tcGrid, 256, GSM_TOTAL>>>(pA, WHI(0), WLO(0), b1a, pB, NN);
    stats_kernel<<<256, 256>>>(pB);
    finalize_bn_kernel<<<1, 128>>>(g1, be1, invN);
    bn_relu_kernel<<<copyGrid, 256>>>((float4*)pB, n4);
    gemm_wmma_kernel<true><<<tcGrid, 256, GSM_TOTAL>>>(pB, WHI(1), WLO(1), b2a, pC, NN);

    // ---- conv2 ----
    copy4_kernel<<<copyGrid, 256>>>((float4*)pA, (const float4*)pC, n4);
    scatter_add_kernel<<<scatGrid, 256>>>(pC, ei, pA, EE);
    zero_stats_kernel<<<1, 128>>>();
    gemm_wmma_kernel<false><<<tcGrid, 256, GSM_TOTAL>>>(pA, WHI(2), WLO(2), b1b, pB, NN);
    stats_kernel<<<256, 256>>>(pB);
    finalize_bn_kernel<<<1, 128>>>(g2, be2, invN);
    bn_relu_kernel<<<copyGrid, 256>>>((float4*)pB, n4);
    gemm_wmma_kernel<true><<<tcGrid, 256, GSM_TOTAL>>>(pB, WHI(3), WLO(3), b2b, pC, NN);

    // ---- head ----
    gemm_wmma_kernel<true><<<tcGrid, 256, GSM_TOTAL>>>(pC, WHI(4), WLO(4), bl1, pA, NN);
    gemm40_kernel<<<(NN + 127) / 128, 320>>>(pA, Wl2, bl2, pB, NN);
    logsoftmax40_kernel<<<(NN + 255) / 256, 256>>>(pB, out, NN);
}

// round 7
// speedup vs baseline: 1.7779x; 1.1945x over previous
#include <cuda_runtime.h>
#include <cuda_bf16.h>
#include <mma.h>
#include <math.h>
#include <stdint.h>

using namespace nvcuda;

#define NN 50000
#define EE 800000
#define DH 128
#define DOUT 40
#define WLD 136   // padded leading dim for bf16 tiles

// ---------------- scratch (device globals; no allocation allowed) ----------------
__device__ float g_bufA[NN * DH];
__device__ float g_bufB[NN * DH];
__device__ float g_bufC[NN * DH];
__device__ float g_sum[DH];
__device__ float g_sqsum[DH];
__device__ float g_scale[DH];
__device__ float g_shift[DH];
__device__ int   g_deg[NN];
__device__ int   g_off[NN + 1];
__device__ int   g_cursor[NN];
__device__ int   g_slot[EE];
__device__ __nv_bfloat16 g_Wbf[5][2][128 * WLD];

// ---------------- CSR build ----------------
__global__ void hist_kernel(const int* __restrict__ ei) {
    int e = blockIdx.x * blockDim.x + threadIdx.x;
    if (e >= EE) return;
    int dst = min(max(__ldg(&ei[EE + e]), 0), NN - 1);
    atomicAdd(&g_deg[dst], 1);
}

__global__ void __launch_bounds__(1024) scan_kernel() {
    const int CH = (NN + 1023) / 1024;   // 49
    int t = threadIdx.x;
    int base = t * CH;
    int s = 0;
    for (int i = 0; i < CH; i++) {
        int idx = base + i;
        if (idx < NN) s += g_deg[idx];
    }
    __shared__ int sh[1024];
    sh[t] = s;
    __syncthreads();
    for (int off = 1; off < 1024; off <<= 1) {
        int v = (t >= off) ? sh[t - off] : 0;
        __syncthreads();
        sh[t] += v;
        __syncthreads();
    }
    int run = sh[t] - s;   // exclusive
    for (int i = 0; i < CH; i++) {
        int idx = base + i;
        if (idx < NN) {
            g_off[idx] = run;
            g_cursor[idx] = run;
            run += g_deg[idx];
        }
    }
    if (t == 1023) g_off[NN] = run;
}

__global__ void fill_kernel(const int* __restrict__ ei) {
    int e = blockIdx.x * blockDim.x + threadIdx.x;
    if (e >= EE) return;
    int src = min(max(__ldg(&ei[e]), 0), NN - 1);
    int dst = min(max(__ldg(&ei[EE + e]), 0), NN - 1);
    int pos = atomicAdd(&g_cursor[dst], 1);
    g_slot[pos] = src;
}

// ---------------- aggregation: warp per node, agg[i] = x[i] + sum_nbr x[nbr] ----------
__global__ void __launch_bounds__(256) aggregate_kernel(const float* __restrict__ X,
                                                        float* __restrict__ agg) {
    int node = blockIdx.x * 8 + (threadIdx.x >> 5);
    if (node >= NN) return;
    int lane = threadIdx.x & 31;
    const float4* X4 = (const float4*)X;
    float4 a = __ldg(&X4[(size_t)node * 32 + lane]);
    int s = __ldg(&g_off[node]);
    int e = __ldg(&g_off[node + 1]);
    for (int j = s; j < e; j++) {
        int src = __ldg(&g_slot[j]);
        float4 v = __ldg(&X4[(size_t)src * 32 + lane]);
        a.x += v.x; a.y += v.y; a.z += v.z; a.w += v.w;
    }
    ((float4*)agg)[(size_t)node * 32 + lane] = a;
}

// ---------------- W prep ----------------
__global__ void prep_w_kernel(const float* W0, const float* W1, const float* W2,
                              const float* W3, const float* W4) {
    const float* Ws[5] = {W0, W1, W2, W3, W4};
    const float* W = Ws[blockIdx.x];
    __nv_bfloat16* hi = g_Wbf[blockIdx.x][0];
    __nv_bfloat16* lo = g_Wbf[blockIdx.x][1];
    for (int idx = threadIdx.x; idx < 128 * 128; idx += blockDim.x) {
        int k = idx >> 7;
        int n = idx & 127;
        float w = __ldg(&W[idx]);
        __nv_bfloat16 h = __float2bfloat16(w);
        __nv_bfloat16 l = __float2bfloat16(w - __bfloat162float(h));
        hi[k * WLD + n] = h;
        lo[k * WLD + n] = l;
    }
}

// ---------------- stats helpers ----------------
__global__ void zero_stats_kernel() {
    int c = threadIdx.x;
    if (c < DH) { g_sum[c] = 0.f; g_sqsum[c] = 0.f; }
}

__global__ void finalize_bn_kernel(const float* __restrict__ gamma,
                                   const float* __restrict__ beta, float invN) {
    int c = threadIdx.x;
    if (c < DH) {
        float mu  = g_sum[c] * invN;
        float var = g_sqsum[c] * invN - mu * mu;
        float rs  = rsqrtf(var + 1e-5f);
        float sc  = rs * __ldg(&gamma[c]);
        g_scale[c] = sc;
        g_shift[c] = __ldg(&beta[c]) - mu * sc;
    }
}

// ---------------- tensor-core GEMM (wmma bf16 hi/lo 3-term, fp32 accum) --------------
// 256 threads (8 warps), 128 rows/CTA, full 128x128 tile.
// BN_IN: apply g_scale/g_shift + relu to input during bf16 convert.
// STATS: accumulate column sum/sqsum of output into g_sum/g_sqsum.
static const int GSM_TOTAL = 512 + 4 * 128 * WLD * 2;   // 139776

template <bool RELU, bool STATS, bool BN_IN>
__global__ void __launch_bounds__(256) gemm_wmma_kernel(
    const float* __restrict__ X,
    const __nv_bfloat16* __restrict__ Whi,
    const __nv_bfloat16* __restrict__ Wlo,
    const float* __restrict__ Bias,
    float* __restrict__ Y, int nrows)
{
    extern __shared__ char smem[];
    float* sbias = (float*)smem;
    __nv_bfloat16* Ahi = (__nv_bfloat16*)(smem + 512);
    __nv_bfloat16* Alo = Ahi + 128 * WLD;
    __nv_bfloat16* Bhi = Alo + 128 * WLD;
    __nv_bfloat16* Blo = Bhi + 128 * WLD;
    float* sout = (float*)(smem + 512);   // reused after MMA

    int tid  = threadIdx.x;
    int row0 = blockIdx.x * 128;

    if (tid < 128) sbias[tid] = __ldg(&Bias[tid]);

    // W hi/lo tiles -> smem
    {
        const uint4* sh = (const uint4*)Whi;
        const uint4* sl = (const uint4*)Wlo;
        uint4* dh = (uint4*)Bhi;
        uint4* dl = (uint4*)Blo;
#pragma unroll
        for (int i = 0; i < 9; i++) {
            int j = tid + i * 256;
            if (j < 2176) { dh[j] = __ldg(&sh[j]); dl[j] = __ldg(&sl[j]); }
        }
    }

    // X tile -> bf16 hi/lo (optional BN+relu on the fly)
    {
        const float4* X4 = (const float4*)X;
        int c4 = tid & 31;
        float4 sc, sh4;
        if (BN_IN) {
            sc  = ((const float4*)g_scale)[c4];
            sh4 = ((const float4*)g_shift)[c4];
        }
#pragma unroll
        for (int i = 0; i < 16; i++) {
            int idx = tid + i * 256;
            int r  = idx >> 5;
            int grow = row0 + r;
            float4 v = make_float4(0.f, 0.f, 0.f, 0.f);
            if (grow < nrows) v = __ldg(&X4[(size_t)grow * 32 + c4]);
            if (BN_IN) {
                v.x = fmaxf(v.x * sc.x + sh4.x, 0.f);
                v.y = fmaxf(v.y * sc.y + sh4.y, 0.f);
                v.z = fmaxf(v.z * sc.z + sh4.z, 0.f);
                v.w = fmaxf(v.w * sc.w + sh4.w, 0.f);
            }
            __nv_bfloat16 h0 = __float2bfloat16(v.x), h1 = __float2bfloat16(v.y),
                          h2 = __float2bfloat16(v.z), h3 = __float2bfloat16(v.w);
            __nv_bfloat16 l0 = __float2bfloat16(v.x - __bfloat162float(h0));
            __nv_bfloat16 l1 = __float2bfloat16(v.y - __bfloat162float(h1));
            __nv_bfloat16 l2 = __float2bfloat16(v.z - __bfloat162float(h2));
            __nv_bfloat16 l3 = __float2bfloat16(v.w - __bfloat162float(h3));
            __nv_bfloat16* ph = Ahi + r * WLD + c4 * 4;
            __nv_bfloat16* pl = Alo + r * WLD + c4 * 4;
            ph[0] = h0; ph[1] = h1; ph[2] = h2; ph[3] = h3;
            pl[0] = l0; pl[1] = l1; pl[2] = l2; pl[3] = l3;
        }
    }
    __syncthreads();

    // MMA: warp w -> rows (w&3)*32..+32, cols (w>>2)*64..+64
    int w  = tid >> 5;
    int wr = (w & 3) * 32;
    int wc = (w >> 2) * 64;

    wmma::fragment<wmma::accumulator, 16, 16, 16, float> acc[2][4];
#pragma unroll
    for (int i = 0; i < 2; i++)
#pragma unroll
        for (int j = 0; j < 4; j++) wmma::fill_fragment(acc[i][j], 0.f);

#pragma unroll
    for (int k = 0; k < 8; k++) {
        wmma::fragment<wmma::matrix_a, 16, 16, 16, __nv_bfloat16, wmma::row_major> ah[2], al[2];
        wmma::fragment<wmma::matrix_b, 16, 16, 16, __nv_bfloat16, wmma::row_major> bh[4], bl[4];
#pragma unroll
        for (int i = 0; i < 2; i++) {
            wmma::load_matrix_sync(ah[i], Ahi + (wr + 16 * i) * WLD + k * 16, WLD);
            wmma::load_matrix_sync(al[i], Alo + (wr + 16 * i) * WLD + k * 16, WLD);
        }
#pragma unroll
        for (int j = 0; j < 4; j++) {
            wmma::load_matrix_sync(bh[j], Bhi + (k * 16) * WLD + wc + 16 * j, WLD);
            wmma::load_matrix_sync(bl[j], Blo + (k * 16) * WLD + wc + 16 * j, WLD);
        }
#pragma unroll
        for (int i = 0; i < 2; i++)
#pragma unroll
            for (int j = 0; j < 4; j++) {
                wmma::mma_sync(acc[i][j], ah[i], bh[j], acc[i][j]);
                wmma::mma_sync(acc[i][j], ah[i], bl[j], acc[i][j]);
                wmma::mma_sync(acc[i][j], al[i], bh[j], acc[i][j]);
            }
    }
    __syncthreads();

#pragma unroll
    for (int i = 0; i < 2; i++)
#pragma unroll
        for (int j = 0; j < 4; j++)
            wmma::store_matrix_sync(sout + (wr + 16 * i) * 132 + wc + 16 * j,
                                    acc[i][j], 132, wmma::mem_row_major);
    __syncthreads();

    // bias + relu + global write (+ column stats)
    float cs[4] = {0.f, 0.f, 0.f, 0.f};
    float cq[4] = {0.f, 0.f, 0.f, 0.f};
    {
        float4* Y4 = (float4*)Y;
        int c4 = tid & 31;
        float4 b = ((const float4*)sbias)[c4];
#pragma unroll
        for (int i = 0; i < 16; i++) {
            int idx = tid + i * 256;
            int r  = idx >> 5;
            int grow = row0 + r;
            if (grow >= nrows) continue;
            float4 v = ((const float4*)(sout + r * 132))[c4];
            v.x += b.x; v.y += b.y; v.z += b.z; v.w += b.w;
            if (RELU) {
                v.x = fmaxf(v.x, 0.f); v.y = fmaxf(v.y, 0.f);
                v.z = fmaxf(v.z, 0.f); v.w = fmaxf(v.w, 0.f);
            }
            if (STATS) {
                cs[0] += v.x; cq[0] += v.x * v.x;
                cs[1] += v.y; cq[1] += v.y * v.y;
                cs[2] += v.z; cq[2] += v.z * v.z;
                cs[3] += v.w; cq[3] += v.w * v.w;
            }
            Y4[(size_t)grow * 32 + c4] = v;
        }
    }

    if (STATS) {
        __syncthreads();
        float* ssum = sout;           // [8][128]
        float* ssq  = sout + 1024;    // [8][128]
        int g  = tid >> 5;
        int c4 = tid & 31;
#pragma unroll
        for (int j = 0; j < 4; j++) {
            ssum[g * 128 + c4 * 4 + j] = cs[j];
            ssq[g * 128 + c4 * 4 + j]  = cq[j];
        }
        __syncthreads();
        if (tid < 128) {
            float a = 0.f;
#pragma unroll
            for (int gg = 0; gg < 8; gg++) a += ssum[gg * 128 + tid];
            atomicAdd(&g_sum[tid], a);
        } else {
            int c = tid - 128;
            float a = 0.f;
#pragma unroll
            for (int gg = 0; gg < 8; gg++) a += ssq[gg * 128 + c];
            atomicAdd(&g_sqsum[c], a);
        }
    }
}

// ---------------- fused head: logits = X @ Wl2 + b, then log-softmax ----------------
__global__ void __launch_bounds__(320) gemm40_softmax_kernel(
    const float* __restrict__ X, const float* __restrict__ W,
    const float* __restrict__ B, float* __restrict__ out, int nrows)
{
    __shared__ float slog[128 * 44];

    int t  = threadIdx.x;
    int rg = t / 10;
    int cg = t - rg * 10;
    int row0 = blockIdx.x * 128 + rg * 4;

    const float4* X4 = (const float4*)X;
    const float4* W4 = (const float4*)W;

    int  rowc[4];
    bool val[4];
#pragma unroll
    for (int r = 0; r < 4; r++) {
        int rr = row0 + r;
        val[r]  = rr < nrows;
        rowc[r] = val[r] ? rr : 0;
    }

    float acc[4][4];
#pragma unroll
    for (int r = 0; r < 4; r++)
#pragma unroll
        for (int j = 0; j < 4; j++) acc[r][j] = 0.f;

#pragma unroll 4
    for (int k = 0; k < 128; k += 4) {
        float4 w0 = W4[(k + 0) * 10 + cg];
        float4 w1 = W4[(k + 1) * 10 + cg];
        float4 w2 = W4[(k + 2) * 10 + cg];
        float4 w3 = W4[(k + 3) * 10 + cg];
#pragma unroll
        for (int r = 0; r < 4; r++) {
            float4 xv = X4[rowc[r] * 32 + (k >> 2)];
            acc[r][0] += xv.x * w0.x; acc[r][0] += xv.y * w1.x;
            acc[r][0] += xv.z * w2.x; acc[r][0] += xv.w * w3.x;
            acc[r][1] += xv.x * w0.y; acc[r][1] += xv.y * w1.y;
            acc[r][1] += xv.z * w2.y; acc[r][1] += xv.w * w3.y;
            acc[r][2] += xv.x * w0.z; acc[r][2] += xv.y * w1.z;
            acc[r][2] += xv.z * w2.z; acc[r][2] += xv.w * w3.z;
            acc[r][3] += xv.x * w0.w; acc[r][3] += xv.y * w1.w;
            acc[r][3] += xv.z * w2.w; acc[r][3] += xv.w * w3.w;
        }
    }

    float4 b4 = ((const float4*)B)[cg];
#pragma unroll
    for (int r = 0; r < 4; r++) {
        int lr = rg * 4 + r;
        slog[lr * 44 + cg * 4 + 0] = acc[r][0] + b4.x;
        slog[lr * 44 + cg * 4 + 1] = acc[r][1] + b4.y;
        slog[lr * 44 + cg * 4 + 2] = acc[r][2] + b4.z;
        slog[lr * 44 + cg * 4 + 3] = acc[r][3] + b4.w;
    }
    __syncthreads();

    if (t < 128) {
        int grow = blockIdx.x * 128 + t;
        if (grow < nrows) {
            const float* l = slog + t * 44;
            float v[DOUT];
#pragma unroll
            for (int j = 0; j < DOUT; j++) v[j] = l[j];
            float m = v[0];
#pragma unroll
            for (int j = 1; j < DOUT; j++) m = fmaxf(m, v[j]);
            float s = 0.f;
#pragma unroll
            for (int j = 0; j < DOUT; j++) s += expf(v[j] - m);
            float lse = logf(s) + m;
            float4* o4 = (float4*)(out + (size_t)grow * DOUT);
#pragma unroll
            for (int i = 0; i < 10; i++) {
                float4 o;
                o.x = v[i*4+0] - lse; o.y = v[i*4+1] - lse;
                o.z = v[i*4+2] - lse; o.w = v[i*4+3] - lse;
                o4[i] = o;
            }
        }
    }
}

// ---------------- host launch ----------------
extern "C" void kernel_launch(void* const* d_in, const int* in_sizes, int n_in,
                              void* d_out, int out_size) {
    const float* x   = (const float*)d_in[0];
    const int*   ei  = (const int*)d_in[1];   // int32
    const float* W1a = (const float*)d_in[2];
    const float* b1a = (const float*)d_in[3];
    const float* g1  = (const float*)d_in[4];
    const float* be1 = (const float*)d_in[5];
    const float* W2a = (const float*)d_in[6];
    const float* b2a = (const float*)d_in[7];
    const float* W1b = (const float*)d_in[8];
    const float* b1b = (const float*)d_in[9];
    const float* g2  = (const float*)d_in[10];
    const float* be2 = (const float*)d_in[11];
    const float* W2b = (const float*)d_in[12];
    const float* b2b = (const float*)d_in[13];
    const float* Wl1 = (const float*)d_in[14];
    const float* bl1 = (const float*)d_in[15];
    const float* Wl2 = (const float*)d_in[16];
    const float* bl2 = (const float*)d_in[17];
    float* out = (float*)d_out;

    float *pA, *pB, *pC;
    cudaGetSymbolAddress((void**)&pA, g_bufA);
    cudaGetSymbolAddress((void**)&pB, g_bufB);
    cudaGetSymbolAddress((void**)&pC, g_bufC);
    __nv_bfloat16* wt;
    cudaGetSymbolAddress((void**)&wt, g_Wbf);
    int* pDeg;
    cudaGetSymbolAddress((void**)&pDeg, g_deg);

    cudaFuncSetAttribute(gemm_wmma_kernel<false, true,  false>, cudaFuncAttributeMaxDynamicSharedMemorySize, GSM_TOTAL);
    cudaFuncSetAttribute(gemm_wmma_kernel<true,  false, true >, cudaFuncAttributeMaxDynamicSharedMemorySize, GSM_TOTAL);
    cudaFuncSetAttribute(gemm_wmma_kernel<true,  false, false>, cudaFuncAttributeMaxDynamicSharedMemorySize, GSM_TOTAL);

    const int edgeGrid = (EE + 255) / 256;
    const int aggGrid  = (NN + 7) / 8;
    const int tcGrid   = (NN + 127) / 128;
    const float invN = 1.0f / (float)NN;
    const size_t wpage = (size_t)128 * WLD;

    // weight prep + CSR build (once; reused by both convs)
    prep_w_kernel<<<5, 256>>>(W1a, W2a, W1b, W2b, Wl1);
    cudaMemsetAsync(pDeg, 0, NN * sizeof(int));
    hist_kernel<<<edgeGrid, 256>>>(ei);
    scan_kernel<<<1, 1024>>>();
    fill_kernel<<<edgeGrid, 256>>>(ei);
#define WHI(p) (wt + (size_t)(p) * 2 * wpage)
#define WLO(p) (wt + (size_t)(p) * 2 * wpage + wpage)

    // ---- conv1 ----
    aggregate_kernel<<<aggGrid, 256>>>(x, pA);
    zero_stats_kernel<<<1, 128>>>();
    gemm_wmma_kernel<false, true, false><<<tcGrid, 256, GSM_TOTAL>>>(pA, WHI(0), WLO(0), b1a, pB, NN);
    finalize_bn_kernel<<<1, 128>>>(g1, be1, invN);
    gemm_wmma_kernel<true, false, true><<<tcGrid, 256, GSM_TOTAL>>>(pB, WHI(1), WLO(1), b2a, pC, NN);

    // ---- conv2 ----
    aggregate_kernel<<<aggGrid, 256>>>(pC, pA);
    zero_stats_kernel<<<1, 128>>>();
    gemm_wmma_kernel<false, true, false><<<tcGrid, 256, GSM_TOTAL>>>(pA, WHI(2), WLO(2), b1b, pB, NN);
    finalize_bn_kernel<<<1, 128>>>(g2, be2, invN);
    gemm_wmma_kernel<true, false, true><<<tcGrid, 256, GSM_TOTAL>>>(pB, WHI(3), WLO(3), b2b, pC, NN);

    // ---- head ----
    gemm_wmma_kernel<true, false, false><<<tcGrid, 256, GSM_TOTAL>>>(pC, WHI(4), WLO(4), bl1, pA, NN);
    gemm40_softmax_kernel<<<tcGrid, 320>>>(pA, Wl2, bl2, out, NN);
}